// round 2
// baseline (speedup 1.0000x reference)
#include <cuda_runtime.h>

#define T_STEPS 8192
#define N_CH    4096
#define DT      0.01f
#define CHUNKS  128
#define CHUNK_L (T_STEPS / CHUNKS)   // 64
#define LOG2_L  6                    // 64 = 2^6

// Scratch (no cudaMalloc allowed): chunk aggregates and chunk-boundary states.
__device__ float g_B[CHUNKS * N_CH];   // B_k per (chunk, channel): 2 MiB
__device__ float g_S[CHUNKS * N_CH];   // s_in per (chunk, channel): 2 MiB

// ---------------------------------------------------------------------------
// Pass A: per-chunk aggregate B_k(j) = sum_{i<L} c^{L-1-i} * a * x[t0+i, j]
// computed by the same recurrence B = c*B + a*x starting at 0.
// Each thread owns 4 consecutive channels (float4).
// ---------------------------------------------------------------------------
__global__ void __launch_bounds__(128) passA(const float* __restrict__ x,
                                             const float* __restrict__ tau) {
    const int j = (blockIdx.x * blockDim.x + threadIdx.x) * 4;   // channel base
    const int k = blockIdx.y;                                     // chunk id

    const float4 tv = *reinterpret_cast<const float4*>(tau + j);
    const float a0 = DT / fmaxf(tv.x, DT), c0 = 1.0f - a0;
    const float a1 = DT / fmaxf(tv.y, DT), c1 = 1.0f - a1;
    const float a2 = DT / fmaxf(tv.z, DT), c2 = 1.0f - a2;
    const float a3 = DT / fmaxf(tv.w, DT), c3 = 1.0f - a3;

    float b0 = 0.f, b1 = 0.f, b2 = 0.f, b3 = 0.f;
    const float* xp = x + (size_t)k * CHUNK_L * N_CH + j;

#pragma unroll 8
    for (int t = 0; t < CHUNK_L; ++t) {
        const float4 xv = *reinterpret_cast<const float4*>(xp + (size_t)t * N_CH);
        b0 = fmaf(c0, b0, a0 * xv.x);
        b1 = fmaf(c1, b1, a1 * xv.y);
        b2 = fmaf(c2, b2, a2 * xv.z);
        b3 = fmaf(c3, b3, a3 * xv.w);
    }
    float4 out; out.x = b0; out.y = b1; out.z = b2; out.w = b3;
    *reinterpret_cast<float4*>(g_B + (size_t)k * N_CH + j) = out;
}

// ---------------------------------------------------------------------------
// Pass B: serial scan over chunk boundaries. One thread per channel.
// s_in[0] = x[0, j]; s_in[k+1] = c^L * s_in[k] + B_k.
// ---------------------------------------------------------------------------
__global__ void __launch_bounds__(128) passB(const float* __restrict__ x,
                                             const float* __restrict__ tau) {
    const int j = blockIdx.x * blockDim.x + threadIdx.x;   // channel
    const float a = DT / fmaxf(tau[j], DT);
    const float c = 1.0f - a;
    float cl = c;
#pragma unroll
    for (int p = 0; p < LOG2_L; ++p) cl *= cl;             // c^64

    float s = x[j];                                        // s_0 = input[0, j]
#pragma unroll 4
    for (int k = 0; k < CHUNKS; ++k) {
        g_S[(size_t)k * N_CH + j] = s;
        s = fmaf(cl, s, g_B[(size_t)k * N_CH + j]);
    }
}

// ---------------------------------------------------------------------------
// Pass C: replay each chunk from its known boundary state, write out = s+bias.
// ---------------------------------------------------------------------------
__global__ void __launch_bounds__(128) passC(const float* __restrict__ x,
                                             const float* __restrict__ tau,
                                             const float* __restrict__ bias,
                                             float* __restrict__ out) {
    const int j = (blockIdx.x * blockDim.x + threadIdx.x) * 4;
    const int k = blockIdx.y;

    const float4 tv = *reinterpret_cast<const float4*>(tau + j);
    const float a0 = DT / fmaxf(tv.x, DT), c0 = 1.0f - a0;
    const float a1 = DT / fmaxf(tv.y, DT), c1 = 1.0f - a1;
    const float a2 = DT / fmaxf(tv.z, DT), c2 = 1.0f - a2;
    const float a3 = DT / fmaxf(tv.w, DT), c3 = 1.0f - a3;
    const float4 bv = *reinterpret_cast<const float4*>(bias + j);

    float4 s = *reinterpret_cast<const float4*>(g_S + (size_t)k * N_CH + j);

    const float* xp = x   + (size_t)k * CHUNK_L * N_CH + j;
    float*       op = out + (size_t)k * CHUNK_L * N_CH + j;

#pragma unroll 8
    for (int t = 0; t < CHUNK_L; ++t) {
        const float4 xv = *reinterpret_cast<const float4*>(xp + (size_t)t * N_CH);
        s.x = fmaf(c0, s.x, a0 * xv.x);
        s.y = fmaf(c1, s.y, a1 * xv.y);
        s.z = fmaf(c2, s.z, a2 * xv.z);
        s.w = fmaf(c3, s.w, a3 * xv.w);
        float4 o;
        o.x = s.x + bv.x; o.y = s.y + bv.y; o.z = s.z + bv.z; o.w = s.w + bv.w;
        *reinterpret_cast<float4*>(op + (size_t)t * N_CH) = o;
    }
}

extern "C" void kernel_launch(void* const* d_in, const int* in_sizes, int n_in,
                              void* d_out, int out_size) {
    const float* x    = (const float*)d_in[0];   // [T, N]
    const float* tau  = (const float*)d_in[1];   // [N]
    const float* bias = (const float*)d_in[2];   // [N]
    float*       out  = (float*)d_out;           // [T*N]

    // Pass A: grid (N/(128*4), CHUNKS) = (8, 128), 128 thr
    dim3 gA(N_CH / (128 * 4), CHUNKS);
    passA<<<gA, 128>>>(x, tau);

    // Pass B: one thread per channel
    passB<<<N_CH / 128, 128>>>(x, tau);

    // Pass C: same shape as A
    passC<<<gA, 128>>>(x, tau, bias, out);
}

// round 3
// speedup vs baseline: 1.3592x; 1.3592x over previous
#include <cuda_runtime.h>

#define T_STEPS 8192
#define N_CH    4096
#define DT      0.01f
#define L       64                    // time steps per chunk
#define KCHUNKS (T_STEPS / L)         // 128
#define CPB     128                   // channels per block (1 per thread)
#define SLICES  (N_CH / CPB)          // 32
#define WIN     8                     // lookback window

// Scan state (no cudaMalloc allowed -> __device__ globals)
__device__ float    g_agg [KCHUNKS * N_CH];   // zero-start chunk aggregate
__device__ float    g_pref[KCHUNKS * N_CH];   // inclusive prefix (state at chunk end)
__device__ int      g_flag[KCHUNKS * SLICES]; // 0=empty, 1=agg ready, 2=prefix ready
__device__ unsigned g_ticket;

__global__ void reset_kernel() {
    int i = blockIdx.x * blockDim.x + threadIdx.x;
    if (i < KCHUNKS * SLICES) g_flag[i] = 0;
    if (i == 0) g_ticket = 0u;
}

__device__ __forceinline__ float ldcg(const float* p) {
    float v; asm volatile("ld.global.cg.f32 %0, [%1];" : "=f"(v) : "l"(p)); return v;
}
__device__ __forceinline__ void stcg(float* p, float v) {
    asm volatile("st.global.cg.f32 [%0], %1;" :: "l"(p), "f"(v));
}

__global__ void __launch_bounds__(CPB) scan_kernel(const float* __restrict__ x,
                                                   const float* __restrict__ tau,
                                                   const float* __restrict__ bias,
                                                   float* __restrict__ out) {
    __shared__ unsigned s_vid;
    __shared__ int s_flag[WIN];
    const int tid = threadIdx.x;

    // Ticket: chunk-major virtual block id. Guarantees every ticket-predecessor
    // is resident-or-done -> aggregates always get published -> no deadlock.
    if (tid == 0) s_vid = atomicAdd(&g_ticket, 1u);
    __syncthreads();
    const int vid   = (int)s_vid;
    const int k     = vid / SLICES;       // chunk index (time)
    const int slice = vid % SLICES;       // channel slice
    const int j     = slice * CPB + tid;  // my channel

    const float a = DT / fmaxf(tau[j], DT);
    const float c = 1.0f - a;
    float cl = c;
#pragma unroll
    for (int p = 0; p < 6; ++p) cl *= cl;   // c^64

    const float* xp = x + (size_t)k * L * N_CH + j;

    // ---- Phase 1: zero-start aggregate over my 64 rows ----
    float agg = 0.f;
#pragma unroll 8
    for (int r = 0; r < L; ++r)
        agg = fmaf(c, agg, a * xp[(size_t)r * N_CH]);

    float s_in;
    if (k == 0) {
        s_in = x[j];                       // s_0 = input[0, :]
        stcg(&g_pref[j], fmaf(cl, s_in, agg));
        __syncthreads();
        if (tid == 0) { __threadfence(); atomicExch(&g_flag[slice], 2); }
    } else {
        // publish aggregate immediately (never blocks)
        stcg(&g_agg[(size_t)k * N_CH + j], agg);
        __syncthreads();
        if (tid == 0) { __threadfence(); atomicExch(&g_flag[k * SLICES + slice], 1); }

        // ---- windowed decoupled lookback ----
        float carry = 0.f, factor = 1.f;
        int kk = k - 1;
        bool done = false;
        while (!done) {
            if (tid < WIN) {
                int idx = kk - tid;
                s_flag[tid] = (idx >= 0) ? *(volatile int*)&g_flag[idx * SLICES + slice] : 0;
            }
            __syncthreads();
            int cnt = 0, d = -1;
#pragma unroll
            for (int i = 0; i < WIN; ++i) {
                int f = s_flag[i];
                if (f == 0) break;
                cnt = i + 1;
                if (f == 2) { d = i; break; }
            }
            __syncthreads();
            if (cnt > 0) {
                __threadfence();   // acquire: order value loads after flag observation
                for (int i = 0; i < cnt; ++i) {
                    float v = (i == d) ? ldcg(&g_pref[(size_t)(kk - i) * N_CH + j])
                                       : ldcg(&g_agg [(size_t)(kk - i) * N_CH + j]);
                    carry = fmaf(factor, v, carry);
                    if (i == d) { done = true; break; }
                    factor *= cl;
                }
                kk -= cnt;
            }
        }
        s_in = carry;

        // publish inclusive prefix (state at end of my chunk)
        stcg(&g_pref[(size_t)k * N_CH + j], fmaf(cl, s_in, agg));
        __syncthreads();
        if (tid == 0) { __threadfence(); atomicExch(&g_flag[k * SLICES + slice], 2); }
    }

    // ---- Phase 2: replay tile from true s_in (x re-read hits L1/L2), stream out ----
    const float b = bias[j];
    float s = s_in;
    float* op = out + (size_t)k * L * N_CH + j;
#pragma unroll 8
    for (int r = 0; r < L; ++r) {
        s = fmaf(c, s, a * xp[(size_t)r * N_CH]);
        op[(size_t)r * N_CH] = s + b;
    }
}

extern "C" void kernel_launch(void* const* d_in, const int* in_sizes, int n_in,
                              void* d_out, int out_size) {
    const float* x    = (const float*)d_in[0];   // [T, N]
    const float* tau  = (const float*)d_in[1];   // [N]
    const float* bias = (const float*)d_in[2];   // [N]
    float*       out  = (float*)d_out;           // [T*N]

    reset_kernel<<<(KCHUNKS * SLICES + 255) / 256, 256>>>();
    scan_kernel<<<KCHUNKS * SLICES, CPB>>>(x, tau, bias, out);
}